// round 1
// baseline (speedup 1.0000x reference)
#include <cuda_runtime.h>

#define ND 128
#define HD 256
#define LVLS 4
#define TPB 128
#define MPAD 132          // 128 + 4 pad: conflict-free float4 LDS of M columns
#define TOTAL_NODES 52400

// Scratch (device globals — no allocation allowed)
__device__ float g_Mt[LVLS][ND * ND];   // Mt[j*ND+k] = M[k][j] = (Wv@Wo)[k][j]
__device__ float g_c[LVLS][ND];         // c[j] = (bv@Wo)[j]
__device__ unsigned char g_mask[TOTAL_NODES];

__global__ void zero_mask_k(unsigned char* m, int n) {
    int i = blockIdx.x * blockDim.x + threadIdx.x;
    if (i < n) m[i] = 0;
}

__global__ void mark_k(const int* __restrict__ tgt, unsigned char* m, int e) {
    int i = blockIdx.x * blockDim.x + threadIdx.x;
    if (i < e) m[tgt[i]] = 1;
}

// M = Wv @ Wo (stored transposed), c = bv @ Wo. One block per output column j.
__global__ void prep_k(const float* __restrict__ Wv, const float* __restrict__ Wo,
                       const float* __restrict__ bv, float* __restrict__ Mt,
                       float* __restrict__ cv) {
    int j = blockIdx.x;       // 0..127
    int k = threadIdx.x;      // 0..127
    float s = 0.f;
    #pragma unroll 4
    for (int t = 0; t < HD; t++)
        s += Wv[k * HD + t] * Wo[t * ND + j];
    Mt[j * ND + k] = s;       // Mt[j][k] = M[k][j]
    if (k == 0) {
        float c = 0.f;
        for (int t = 0; t < HD; t++) c += bv[t] * Wo[t * ND + j];
        cv[j] = c;
    }
}

// Main fused kernel: per level, out = LN(nodes + mask*(nodes@M + c) + bo)*gamma + beta
__global__ __launch_bounds__(TPB)
void level_k(const float* __restrict__ nodes, const unsigned char* __restrict__ mask,
             const float* __restrict__ Mt, const float* __restrict__ cv,
             const float* __restrict__ bo, const float* __restrict__ gamma,
             const float* __restrict__ beta, float* __restrict__ out,
             int N, int npb) {
    extern __shared__ float sm[];
    float* Mt_s = sm;                       // ND * MPAD
    float* rows = Mt_s + ND * MPAD;         // 8 * ND (also holds x for LN)
    float* c_s  = rows + 8 * ND;
    float* bo_s = c_s + ND;
    float* g_s  = bo_s + ND;
    float* b_s  = g_s + ND;
    float* mu_s = b_s + ND;                 // 8
    float* rs_s = mu_s + 8;                 // 8

    const int tid = threadIdx.x;

    // Stage M^T with padding (coalesced GMEM reads, conflict-free SMEM writes)
    for (int i = tid; i < ND * ND; i += TPB) {
        int j = i >> 7, k = i & 127;
        Mt_s[j * MPAD + k] = Mt[i];
    }
    c_s[tid] = cv[tid];
    bo_s[tid] = bo[tid];
    g_s[tid] = gamma[tid];
    b_s[tid] = beta[tid];
    __syncthreads();

    const float4* mrow = reinterpret_cast<const float4*>(Mt_s + tid * MPAD); // 528B: 16B aligned
    float4* rows4 = reinterpret_cast<float4*>(rows);
    const float4* nodes4 = reinterpret_cast<const float4*>(nodes);

    const int base0 = blockIdx.x * npb;
    for (int c0 = 0; c0 < npb; c0 += 8) {
        const int base = base0 + c0;
        if (base >= N) break;

        // Load 8 node rows (1024 floats) via float4, coalesced
        #pragma unroll
        for (int r = 0; r < 2; r++) {
            int idx = tid + r * TPB;          // 0..255
            int n = idx >> 5, kk = idx & 31;
            int node = base + n;
            rows4[n * 32 + kk] = (node < N) ? nodes4[node * 32 + kk]
                                            : make_float4(0.f, 0.f, 0.f, 0.f);
        }
        __syncthreads();

        // Matvec: thread tid owns output column j=tid; 8-node register blocking.
        float acc[8] = {0.f, 0.f, 0.f, 0.f, 0.f, 0.f, 0.f, 0.f};
        #pragma unroll 4
        for (int kk = 0; kk < 32; kk++) {
            float4 m = mrow[kk];              // conflict-free (MPAD)
            #pragma unroll
            for (int n = 0; n < 8; n++) {
                float4 r = rows4[n * 32 + kk]; // broadcast
                acc[n] += m.x * r.x;
                acc[n] += m.y * r.y;
                acc[n] += m.z * r.z;
                acc[n] += m.w * r.w;
            }
        }
        __syncthreads();  // everyone done reading rows before overwrite

        // x = nodes + mask*(nodes@M + c) + bo ; store x back into rows
        #pragma unroll
        for (int n = 0; n < 8; n++) {
            int node = base + n;
            if (node < N) {
                float x = rows[n * ND + tid] + bo_s[tid];
                if (mask[node]) x += acc[n] + c_s[tid];
                rows[n * ND + tid] = x;
            }
        }
        __syncthreads();

        // LayerNorm stats: warp w handles nodes w and w+4
        const int wid = tid >> 5, lane = tid & 31;
        for (int n = wid; n < 8; n += 4) {
            float v0 = rows[n * ND + lane];
            float v1 = rows[n * ND + lane + 32];
            float v2 = rows[n * ND + lane + 64];
            float v3 = rows[n * ND + lane + 96];
            float s  = v0 + v1 + v2 + v3;
            float s2 = v0 * v0 + v1 * v1 + v2 * v2 + v3 * v3;
            #pragma unroll
            for (int o = 16; o > 0; o >>= 1) {
                s  += __shfl_xor_sync(0xffffffffu, s, o);
                s2 += __shfl_xor_sync(0xffffffffu, s2, o);
            }
            if (lane == 0) {
                float mu = s * (1.f / 128.f);
                float var = s2 * (1.f / 128.f) - mu * mu;
                mu_s[n] = mu;
                rs_s[n] = rsqrtf(var + 1e-5f);
            }
        }
        __syncthreads();

        // Normalize + affine, coalesced store
        #pragma unroll
        for (int n = 0; n < 8; n++) {
            int node = base + n;
            if (node < N)
                out[node * ND + tid] =
                    (rows[n * ND + tid] - mu_s[n]) * rs_s[n] * g_s[tid] + b_s[tid];
        }
        __syncthreads();  // rows reused next chunk
    }
}

static const int SMEM_BYTES = (ND * MPAD + 8 * ND + 4 * ND + 16) * (int)sizeof(float);

extern "C" void kernel_launch(void* const* d_in, const int* in_sizes, int n_in,
                              void* d_out, int out_size) {
    (void)n_in; (void)out_size;
    // Input order: (nodes_i, edges_i, edge_index_i) x4, Wq,bq,Wk,bk,Wv,bv,We,be,Wo,bo,gamma,beta
    int NN[LVLS], NE[LVLS], noff[LVLS];
    int cum = 0;
    for (int i = 0; i < LVLS; i++) {
        NN[i] = in_sizes[i * 3] / ND;
        NE[i] = in_sizes[i * 3 + 2] / 2;
        noff[i] = cum;
        cum += NN[i];
    }

    const float* Wv    = (const float*)d_in[16];
    const float* bv    = (const float*)d_in[17];
    const float* Wo    = (const float*)d_in[20];
    const float* bo    = (const float*)d_in[21];
    const float* gamma = (const float*)d_in[22];
    const float* beta  = (const float*)d_in[23];
    float* out = (float*)d_out;

    unsigned char* maskp = nullptr;
    float* Mtp = nullptr;
    float* cp = nullptr;
    cudaGetSymbolAddress((void**)&maskp, g_mask);
    cudaGetSymbolAddress((void**)&Mtp, g_Mt);
    cudaGetSymbolAddress((void**)&cp, g_c);

    cudaFuncSetAttribute(level_k, cudaFuncAttributeMaxDynamicSharedMemorySize, SMEM_BYTES);

    zero_mask_k<<<(cum + 255) / 256, 256>>>(maskp, cum);
    for (int i = 0; i < LVLS; i++) {
        const int* ei = (const int*)d_in[i * 3 + 2];
        mark_k<<<(NE[i] + 255) / 256, 256>>>(ei + NE[i], maskp + noff[i], NE[i]);
        prep_k<<<ND, ND>>>(Wv + (size_t)i * ND * HD, Wo + (size_t)i * HD * ND,
                           bv + (size_t)i * HD, Mtp + (size_t)i * ND * ND, cp + (size_t)i * ND);
    }
    for (int i = 0; i < LVLS; i++) {
        int npb = (NN[i] >= 20000) ? 64 : (NN[i] >= 5000 ? 32 : 8);
        int blocks = (NN[i] + npb - 1) / npb;
        level_k<<<blocks, TPB, SMEM_BYTES>>>(
            (const float*)d_in[i * 3], maskp + noff[i],
            Mtp + (size_t)i * ND * ND, cp + (size_t)i * ND,
            bo + (size_t)i * ND, gamma + (size_t)i * ND, beta + (size_t)i * ND,
            out + (size_t)noff[i] * ND, NN[i], npb);
    }
}

// round 2
// speedup vs baseline: 2.0221x; 2.0221x over previous
#include <cuda_runtime.h>

#define ND 128
#define HD 256
#define LVLS 4
#define TPB 128
#define MPAD 132          // 128 + 4 pad: conflict-free float4/ulonglong2 LDS of M columns
#define TOTAL_NODES 52400

typedef unsigned long long ull;

// Scratch (device globals — no allocation allowed)
__device__ float g_Mt[LVLS][ND * ND];   // Mt[j*ND+k] = M[k][j] = (Wv@Wo)[k][j]
__device__ float g_c[LVLS][ND];         // c[j] = (bv@Wo)[j]
__device__ unsigned char g_mask[TOTAL_NODES];

__device__ __forceinline__ ull ffma2(ull a, ull b, ull c) {
    ull d;
    asm("fma.rn.f32x2 %0, %1, %2, %3;" : "=l"(d) : "l"(a), "l"(b), "l"(c));
    return d;
}
__device__ __forceinline__ float2 upk(ull v) {
    float2 f;
    asm("mov.b64 {%0,%1}, %2;" : "=f"(f.x), "=f"(f.y) : "l"(v));
    return f;
}

__global__ void zero_mask_k(int* m, int n) {
    int i = blockIdx.x * blockDim.x + threadIdx.x;
    if (i < n) m[i] = 0;
}

// One launch for all 4 levels: flat edge index -> level -> scatter mask byte.
__global__ void mark_all_k(const int* __restrict__ t0, const int* __restrict__ t1,
                           const int* __restrict__ t2, const int* __restrict__ t3,
                           int4 ecum, int4 noff, unsigned char* __restrict__ m) {
    int i = blockIdx.x * blockDim.x + threadIdx.x;
    if (i >= ecum.w) return;
    const int* t; int off, no;
    if (i < ecum.x)      { t = t0; off = 0;      no = noff.x; }
    else if (i < ecum.y) { t = t1; off = ecum.x; no = noff.y; }
    else if (i < ecum.z) { t = t2; off = ecum.y; no = noff.z; }
    else                 { t = t3; off = ecum.z; no = noff.w; }
    m[no + t[i - off]] = 1;
}

// Mt = (Wv@Wo)^T and c = bv@Wo for all levels. Grid = 4 levels x 8 k-tiles.
__global__ void prep_all_k(const float* __restrict__ Wv, const float* __restrict__ Wo,
                           const float* __restrict__ bv, float* __restrict__ Mt,
                           float* __restrict__ cv) {
    __shared__ float wv_s[16 * 64];
    __shared__ float wo_s[64 * ND];
    const int lvl = blockIdx.x >> 3, kt = blockIdx.x & 7;
    const float* Wvl = Wv + (size_t)lvl * ND * HD;
    const float* Wol = Wo + (size_t)lvl * HD * ND;
    float* Mtl = Mt + (size_t)lvl * ND * ND;
    const int tid = threadIdx.x;           // 256 threads
    const int j = tid & 127;
    const int lr = (tid >> 7) * 8;         // local k-row base (0 or 8)
    float acc[8] = {0.f, 0.f, 0.f, 0.f, 0.f, 0.f, 0.f, 0.f};

    for (int t0 = 0; t0 < HD; t0 += 64) {
        for (int i = tid; i < 16 * 64; i += 256) {
            int r = i >> 6, c = i & 63;
            wv_s[i] = Wvl[(kt * 16 + r) * HD + t0 + c];      // coalesced
        }
        for (int i = tid; i < 64 * ND; i += 256) {
            int r = i >> 7, c = i & 127;
            wo_s[i] = Wol[(t0 + r) * ND + c];                // coalesced
        }
        __syncthreads();
        #pragma unroll 4
        for (int t = 0; t < 64; t++) {
            float wo = wo_s[t * ND + j];                     // conflict-free
            #pragma unroll
            for (int u = 0; u < 8; u++)
                acc[u] += wv_s[(lr + u) * 64 + t] * wo;      // broadcast
        }
        __syncthreads();
    }
    #pragma unroll
    for (int u = 0; u < 8; u++)
        Mtl[j * ND + kt * 16 + lr + u] = acc[u];             // small scattered store, fine
    if (kt == 0 && tid < ND) {
        const float* bvl = bv + (size_t)lvl * HD;
        float c = 0.f;
        for (int t = 0; t < HD; t++) c += bvl[t] * Wol[t * ND + j];
        cv[lvl * ND + j] = c;
    }
}

__device__ __forceinline__ int sel4(int4 v, int l) {
    return l == 0 ? v.x : l == 1 ? v.y : l == 2 ? v.z : v.w;
}

// Fused all-level kernel: out = LN(nodes + mask*(nodes@M + c) + bo)*gamma + beta
__global__ __launch_bounds__(TPB)
void level_all_k(const float* __restrict__ n0, const float* __restrict__ n1,
                 const float* __restrict__ n2, const float* __restrict__ n3,
                 const unsigned char* __restrict__ maskb, const float* __restrict__ Mtb,
                 const float* __restrict__ cvb, const float* __restrict__ bob,
                 const float* __restrict__ gb, const float* __restrict__ bb,
                 float* __restrict__ out, int4 bstart, int4 noff, int4 ncnt) {
    extern __shared__ float sm[];
    float* Mt_s = sm;                       // ND * MPAD
    float* rows = Mt_s + ND * MPAD;         // 8 * ND (matvec input, then x for LN)
    float* c_s  = rows + 8 * ND;
    float* bo_s = c_s + ND;
    float* g_s  = bo_s + ND;
    float* b_s  = g_s + ND;
    float* mu_s = b_s + ND;                 // 8
    float* rs_s = mu_s + 8;                 // 8

    const int tid = threadIdx.x;
    const int b = blockIdx.x;
    int lvl, b0;
    if (b < bstart.x)      { lvl = 0; b0 = 0; }
    else if (b < bstart.y) { lvl = 1; b0 = bstart.x; }
    else if (b < bstart.z) { lvl = 2; b0 = bstart.y; }
    else                   { lvl = 3; b0 = bstart.z; }

    const float* nodes = lvl == 0 ? n0 : lvl == 1 ? n1 : lvl == 2 ? n2 : n3;
    const int N  = sel4(ncnt, lvl);
    const int nO = sel4(noff, lvl);
    const unsigned char* mask = maskb + nO;
    const float* Mt = Mtb + (size_t)lvl * ND * ND;
    float* outl = out + (size_t)nO * ND;
    const int nodeBase = (b - b0) * 128;    // 16 chunks of 8 nodes per block

    // Stage M^T (coalesced GMEM read, conflict-free SMEM write)
    for (int i = tid; i < ND * ND; i += TPB) {
        int j = i >> 7, k = i & 127;
        Mt_s[j * MPAD + k] = Mt[i];
    }
    c_s[tid]  = cvb[lvl * ND + tid];
    bo_s[tid] = bob[lvl * ND + tid];
    g_s[tid]  = gb[lvl * ND + tid];
    b_s[tid]  = bb[lvl * ND + tid];
    __syncthreads();

    const ulonglong2* mrowU = reinterpret_cast<const ulonglong2*>(Mt_s + tid * MPAD);
    const ulonglong2* rowsU = reinterpret_cast<const ulonglong2*>(rows);
    float4* rows4 = reinterpret_cast<float4*>(rows);
    const float4* nodes4 = reinterpret_cast<const float4*>(nodes);

    for (int c0 = 0; c0 < 128; c0 += 8) {
        const int base = nodeBase + c0;
        if (base >= N) break;

        // Load 8 node rows (1024 floats) via float4, coalesced
        #pragma unroll
        for (int r = 0; r < 2; r++) {
            int idx = tid + r * TPB;          // 0..255
            int n = idx >> 5, kk = idx & 31;
            int node = base + n;
            rows4[n * 32 + kk] = (node < N) ? nodes4[node * 32 + kk]
                                            : make_float4(0.f, 0.f, 0.f, 0.f);
        }
        __syncthreads();

        // Matvec with packed f32x2 FMA: thread owns column j=tid, 8 nodes.
        ull a0[8], a1[8];
        #pragma unroll
        for (int n = 0; n < 8; n++) { a0[n] = 0ull; a1[n] = 0ull; }
        #pragma unroll 8
        for (int kk = 0; kk < 32; kk++) {
            ulonglong2 m = mrowU[kk];               // conflict-free (MPAD)
            #pragma unroll
            for (int n = 0; n < 8; n++) {
                ulonglong2 r = rowsU[n * 32 + kk];  // broadcast
                a0[n] = ffma2(m.x, r.x, a0[n]);
                a1[n] = ffma2(m.y, r.y, a1[n]);
            }
        }
        __syncthreads();  // everyone done reading rows before overwrite

        // x = nodes + mask*(nodes@M + c) + bo ; store x back into rows
        #pragma unroll
        for (int n = 0; n < 8; n++) {
            int node = base + n;
            if (node < N) {
                float x = rows[n * ND + tid] + bo_s[tid];
                if (mask[node]) {
                    float2 p = upk(a0[n]), q = upk(a1[n]);
                    x += (p.x + p.y) + (q.x + q.y) + c_s[tid];
                }
                rows[n * ND + tid] = x;
            }
        }
        __syncthreads();

        // LayerNorm stats: warp w handles nodes w and w+4
        const int wid = tid >> 5, lane = tid & 31;
        for (int n = wid; n < 8; n += 4) {
            float v0 = rows[n * ND + lane];
            float v1 = rows[n * ND + lane + 32];
            float v2 = rows[n * ND + lane + 64];
            float v3 = rows[n * ND + lane + 96];
            float s  = v0 + v1 + v2 + v3;
            float s2 = v0 * v0 + v1 * v1 + v2 * v2 + v3 * v3;
            #pragma unroll
            for (int o = 16; o > 0; o >>= 1) {
                s  += __shfl_xor_sync(0xffffffffu, s, o);
                s2 += __shfl_xor_sync(0xffffffffu, s2, o);
            }
            if (lane == 0) {
                float mu = s * (1.f / 128.f);
                float var = s2 * (1.f / 128.f) - mu * mu;
                mu_s[n] = mu;
                rs_s[n] = rsqrtf(var + 1e-5f);
            }
        }
        __syncthreads();

        // Normalize + affine, coalesced store
        #pragma unroll
        for (int n = 0; n < 8; n++) {
            int node = base + n;
            if (node < N)
                outl[node * ND + tid] =
                    (rows[n * ND + tid] - mu_s[n]) * rs_s[n] * g_s[tid] + b_s[tid];
        }
        __syncthreads();  // rows reused next chunk
    }
}

static const int SMEM_BYTES = (ND * MPAD + 8 * ND + 4 * ND + 16) * (int)sizeof(float);

extern "C" void kernel_launch(void* const* d_in, const int* in_sizes, int n_in,
                              void* d_out, int out_size) {
    (void)n_in; (void)out_size;
    // Inputs: (nodes_i, edges_i, edge_index_i) x4, Wq,bq,Wk,bk,Wv,bv,We,be,Wo,bo,gamma,beta
    int NN[LVLS], NE[LVLS], noffA[LVLS];
    int cumN = 0;
    for (int i = 0; i < LVLS; i++) {
        NN[i] = in_sizes[i * 3] / ND;
        NE[i] = in_sizes[i * 3 + 2] / 2;
        noffA[i] = cumN;
        cumN += NN[i];
    }
    int ec[LVLS]; int cumE = 0;
    for (int i = 0; i < LVLS; i++) { cumE += NE[i]; ec[i] = cumE; }

    const float* Wv    = (const float*)d_in[16];
    const float* bv    = (const float*)d_in[17];
    const float* Wo    = (const float*)d_in[20];
    const float* bo    = (const float*)d_in[21];
    const float* gamma = (const float*)d_in[22];
    const float* beta  = (const float*)d_in[23];
    float* out = (float*)d_out;

    unsigned char* maskp = nullptr;
    float* Mtp = nullptr;
    float* cp = nullptr;
    cudaGetSymbolAddress((void**)&maskp, g_mask);
    cudaGetSymbolAddress((void**)&Mtp, g_Mt);
    cudaGetSymbolAddress((void**)&cp, g_c);

    cudaFuncSetAttribute(level_all_k, cudaFuncAttributeMaxDynamicSharedMemorySize, SMEM_BYTES);

    // 1) zero the mask (word-wide)
    zero_mask_k<<<(cumN / 4 + 255) / 256, 256>>>((int*)maskp, cumN / 4);

    // 2) mark all targets, one launch
    const int* t0 = (const int*)d_in[2]  + NE[0];
    const int* t1 = (const int*)d_in[5]  + NE[1];
    const int* t2 = (const int*)d_in[8]  + NE[2];
    const int* t3 = (const int*)d_in[11] + NE[3];
    int4 ecum = make_int4(ec[0], ec[1], ec[2], ec[3]);
    int4 noff = make_int4(noffA[0], noffA[1], noffA[2], noffA[3]);
    mark_all_k<<<(cumE + 255) / 256, 256>>>(t0, t1, t2, t3, ecum, noff, maskp);

    // 3) prep all levels, one launch
    prep_all_k<<<LVLS * 8, 256>>>(Wv, Wo, bv, Mtp, cp);

    // 4) fused level kernel, one launch
    int bs[LVLS], cumB = 0;
    for (int i = 0; i < LVLS; i++) { cumB += (NN[i] + 127) / 128; bs[i] = cumB; }
    int4 bstart = make_int4(bs[0], bs[1], bs[2], bs[3]);
    int4 ncnt = make_int4(NN[0], NN[1], NN[2], NN[3]);
    level_all_k<<<cumB, TPB, SMEM_BYTES>>>(
        (const float*)d_in[0], (const float*)d_in[3],
        (const float*)d_in[6], (const float*)d_in[9],
        maskp, Mtp, cp, bo, gamma, beta, out, bstart, noff, ncnt);
}